// round 15
// baseline (speedup 1.0000x reference)
#include <cuda_runtime.h>
#include <cuda_bf16.h>
#include <mma.h>
#include <cstdint>

using namespace nvcuda;

#define N_NODES 100000
#define N_EDGES 1600000
#define IN_DIM  128
#define OUT_DIM 64
#define BUCKET_CAP 64
#define M_BLK 128
#define LIN_BLOCKS ((N_NODES + M_BLK - 1) / M_BLK)   // 782
#define N_PAD (LIN_BLOCKS * M_BLK)                   // 100096 (padded rows)
#define LIN_SMEM ((2 * IN_DIM * IN_DIM + 2 * IN_DIM * OUT_DIM) * 2)  // 96 KB

// Scratch (allocation-free rule: __device__ globals)
__device__ float              g_xw[(size_t)N_PAD * OUT_DIM];             // padded for tile stores
__device__ unsigned long long g_bucket[(size_t)N_NODES * BUCKET_CAP];    // 51.2 MB
__device__ int                g_cnt[N_NODES];                            // per-row counts
__device__ float              g_btile[16 * OUT_DIM];                     // bias tile (16 identical rows)

// ---------------------------------------------------------------------------
// btile: 16x64 tile, every row = b (wmma accumulator init -> fused bias).
// ---------------------------------------------------------------------------
__global__ void btile_kernel(const float* __restrict__ b) {
    int i = threadIdx.x;                     // 1024 = 16*64
    g_btile[i] = b[i & 63];
}

// ---------------------------------------------------------------------------
// bf16 tensor-core GEMM, 3-pass fp32 emulation, smem-staged (fixes R13):
//   x = xh + xl, W = wh + wl (bf16 hi + bf16 residual, converted ONCE per
//   element into smem); acc += ah*bh + ah*bl + al*bh  (al*bl ~ 2^-18, dropped)
// Block: 128 nodes x K=128 x N=64. 8 warps; warp w owns m-strip w*16 and all
// 4 n-tiles. Fragments loaded from smem (LDSM), not global.
// ---------------------------------------------------------------------------
__global__ __launch_bounds__(256) void linear_kernel(
    const float* __restrict__ x,
    const float* __restrict__ W,
    float* __restrict__ xw)
{
    extern __shared__ __nv_bfloat16 sh[];
    __nv_bfloat16* XH = sh;                        // 128x128
    __nv_bfloat16* XL = XH + IN_DIM * IN_DIM;      // 128x128
    __nv_bfloat16* WH = XL + IN_DIM * IN_DIM;      // 128x64
    __nv_bfloat16* WL = WH + IN_DIM * OUT_DIM;     // 128x64

    int tid  = threadIdx.x;
    int row0 = blockIdx.x * M_BLK;

    // ---- stage + split x tile (128 rows x 32 float4), convert once ----
    for (int i = tid; i < M_BLK * (IN_DIM / 4); i += 256) {
        int r  = i >> 5;
        int c4 = i & 31;
        float4 v = (row0 + r < N_NODES)
                 ? __ldg(((const float4*)(x + (size_t)(row0 + r) * IN_DIM)) + c4)
                 : make_float4(0.f, 0.f, 0.f, 0.f);
        float vs[4] = {v.x, v.y, v.z, v.w};
        int base = r * IN_DIM + c4 * 4;
        #pragma unroll
        for (int j = 0; j < 4; j++) {
            __nv_bfloat16 h = __float2bfloat16_rn(vs[j]);
            XH[base + j] = h;
            XL[base + j] = __float2bfloat16_rn(vs[j] - __bfloat162float(h));
        }
    }
    // ---- stage + split W (128x64 = 2048 float4) ----
    for (int i = tid; i < (IN_DIM * OUT_DIM) / 4; i += 256) {
        float4 v = __ldg(((const float4*)W) + i);
        float vs[4] = {v.x, v.y, v.z, v.w};
        int base = i * 4;
        #pragma unroll
        for (int j = 0; j < 4; j++) {
            __nv_bfloat16 h = __float2bfloat16_rn(vs[j]);
            WH[base + j] = h;
            WL[base + j] = __float2bfloat16_rn(vs[j] - __bfloat162float(h));
        }
    }
    __syncthreads();

    int w  = tid >> 5;
    int m0 = w * 16;

    wmma::fragment<wmma::accumulator, 16, 16, 16, float> acc[4];
    #pragma unroll
    for (int nt = 0; nt < 4; nt++)
        wmma::load_matrix_sync(acc[nt], g_btile + nt * 16, OUT_DIM, wmma::mem_row_major);

    wmma::fragment<wmma::matrix_a, 16, 16, 16, __nv_bfloat16, wmma::row_major> ah, al;
    wmma::fragment<wmma::matrix_b, 16, 16, 16, __nv_bfloat16, wmma::row_major> bh, bl;

    #pragma unroll 1
    for (int k = 0; k < IN_DIM; k += 16) {
        wmma::load_matrix_sync(ah, XH + m0 * IN_DIM + k, IN_DIM);
        wmma::load_matrix_sync(al, XL + m0 * IN_DIM + k, IN_DIM);
        #pragma unroll
        for (int nt = 0; nt < 4; nt++) {
            wmma::load_matrix_sync(bh, WH + k * OUT_DIM + nt * 16, OUT_DIM);
            wmma::load_matrix_sync(bl, WL + k * OUT_DIM + nt * 16, OUT_DIM);
            wmma::mma_sync(acc[nt], ah, bh, acc[nt]);
            wmma::mma_sync(acc[nt], ah, bl, acc[nt]);
            wmma::mma_sync(acc[nt], al, bh, acc[nt]);
        }
    }

    // stores go to the PADDED xw buffer; rows >= N_NODES land in the pad.
    #pragma unroll
    for (int nt = 0; nt < 4; nt++)
        wmma::store_matrix_sync(xw + (size_t)(row0 + m0) * OUT_DIM + nt * 16,
                                acc[nt], OUT_DIM, wmma::mem_row_major);
}

// ---------------------------------------------------------------------------
// Bucket build: rank = atomicAdd(cnt[row]); {val,col} into fixed 64-slot
// bucket. No histogram, no scan.
// ---------------------------------------------------------------------------
__global__ __launch_bounds__(256) void bucket_kernel(
    const int* __restrict__ erow, const int* __restrict__ ecol,
    const float* __restrict__ eval)
{
    int e = blockIdx.x * blockDim.x + threadIdx.x;
    if (e >= N_EDGES) return;
    int r = erow[e];
    int rank = atomicAdd(&g_cnt[r], 1);
    if (rank < BUCKET_CAP) {
        unsigned long long p =
            ((unsigned long long)(unsigned)__float_as_int(eval[e]) << 32)
            | (unsigned)ecol[e];
        g_bucket[(size_t)r * BUCKET_CAP + rank] = p;
    }
}

// ---------------------------------------------------------------------------
// Gather (PROVEN ~48us): 2 rows/warp, speculative front-batched loads,
// guard-free inner body padded to multiple of 4, rare cnt>32 spill path.
// ---------------------------------------------------------------------------
__global__ __launch_bounds__(256) void gather_kernel(
    const float* __restrict__ xw,
    float4* __restrict__ out)
{
    int warp = (blockIdx.x * 256 + threadIdx.x) >> 5;
    int lane = threadIdx.x & 31;
    int half = lane >> 4;
    int l16  = lane & 15;
    int r0   = warp * 2;
    if (r0 >= N_NODES) return;

    int cnt0 = g_cnt[r0];
    int cnt1 = (r0 + 1 < N_NODES) ? g_cnt[r0 + 1] : 0;
    if (cnt0 > BUCKET_CAP) cnt0 = BUCKET_CAP;
    if (cnt1 > BUCKET_CAP) cnt1 = BUCKET_CAP;
    const unsigned long long* bkt0 = g_bucket + (size_t)r0 * BUCKET_CAP;
    const unsigned long long* bkt1 = bkt0 + BUCKET_CAP;
    unsigned long long p0 = __ldg(&bkt0[lane]);
    unsigned long long p1 = (r0 + 1 < N_NODES) ? __ldg(&bkt1[lane]) : 0;

    #pragma unroll
    for (int rr = 0; rr < 2; rr++) {
        int row = r0 + rr;
        if (row >= N_NODES) break;
        int cnt = rr ? cnt1 : cnt0;
        unsigned long long p = rr ? p1 : p0;

        int rem = cnt < 32 ? cnt : 32;
        if (lane >= rem) p = 0;
        unsigned plo = (unsigned)p;
        unsigned phi = (unsigned)(p >> 32);

        float4 a0 = make_float4(0.f, 0.f, 0.f, 0.f);
        float4 a1 = make_float4(0.f, 0.f, 0.f, 0.f);

        int m4 = (rem + 3) & ~3;
        #pragma unroll 2
        for (int j = 0; j < m4; j += 4) {
            unsigned c0 = __shfl_sync(0xffffffffu, plo, j + half);
            unsigned v0 = __shfl_sync(0xffffffffu, phi, j + half);
            unsigned c1 = __shfl_sync(0xffffffffu, plo, j + 2 + half);
            unsigned v1 = __shfl_sync(0xffffffffu, phi, j + 2 + half);
            float4 x0 = __ldg(((const float4*)(xw + (size_t)c0 * OUT_DIM)) + l16);
            float4 x1 = __ldg(((const float4*)(xw + (size_t)c1 * OUT_DIM)) + l16);
            float f0 = __int_as_float((int)v0);
            float f1 = __int_as_float((int)v1);
            a0.x = fmaf(x0.x, f0, a0.x); a0.y = fmaf(x0.y, f0, a0.y);
            a0.z = fmaf(x0.z, f0, a0.z); a0.w = fmaf(x0.w, f0, a0.w);
            a1.x = fmaf(x1.x, f1, a1.x); a1.y = fmaf(x1.y, f1, a1.y);
            a1.z = fmaf(x1.z, f1, a1.z); a1.w = fmaf(x1.w, f1, a1.w);
        }

        if (cnt > 32) {
            const unsigned long long* bkt = rr ? bkt1 : bkt0;
            int rem2 = cnt - 32;
            unsigned long long q = (lane < rem2) ? __ldg(&bkt[32 + lane]) : 0ULL;
            unsigned qlo = (unsigned)q;
            unsigned qhi = (unsigned)(q >> 32);
            int m42 = (rem2 + 3) & ~3;
            for (int j = 0; j < m42; j += 4) {
                unsigned c0 = __shfl_sync(0xffffffffu, qlo, j + half);
                unsigned v0 = __shfl_sync(0xffffffffu, qhi, j + half);
                unsigned c1 = __shfl_sync(0xffffffffu, qlo, j + 2 + half);
                unsigned v1 = __shfl_sync(0xffffffffu, qhi, j + 2 + half);
                float4 x0 = __ldg(((const float4*)(xw + (size_t)c0 * OUT_DIM)) + l16);
                float4 x1 = __ldg(((const float4*)(xw + (size_t)c1 * OUT_DIM)) + l16);
                float f0 = __int_as_float((int)v0);
                float f1 = __int_as_float((int)v1);
                a0.x = fmaf(x0.x, f0, a0.x); a0.y = fmaf(x0.y, f0, a0.y);
                a0.z = fmaf(x0.z, f0, a0.z); a0.w = fmaf(x0.w, f0, a0.w);
                a1.x = fmaf(x1.x, f1, a1.x); a1.y = fmaf(x1.y, f1, a1.y);
                a1.z = fmaf(x1.z, f1, a1.z); a1.w = fmaf(x1.w, f1, a1.w);
            }
        }

        float4 acc;
        acc.x = a0.x + a1.x; acc.y = a0.y + a1.y;
        acc.z = a0.z + a1.z; acc.w = a0.w + a1.w;
        acc.x += __shfl_xor_sync(0xffffffffu, acc.x, 16);
        acc.y += __shfl_xor_sync(0xffffffffu, acc.y, 16);
        acc.z += __shfl_xor_sync(0xffffffffu, acc.z, 16);
        acc.w += __shfl_xor_sync(0xffffffffu, acc.w, 16);

        if (half == 0) {
            acc.x = fmaxf(acc.x, 0.f);
            acc.y = fmaxf(acc.y, 0.f);
            acc.z = fmaxf(acc.z, 0.f);
            acc.w = fmaxf(acc.w, 0.f);
            out[(size_t)row * (OUT_DIM / 4) + l16] = acc;
        }
    }
}

// ---------------------------------------------------------------------------
static cudaStream_t g_side = nullptr;
static cudaEvent_t  g_evFork = nullptr;
static cudaEvent_t  g_evJoin = nullptr;

extern "C" void kernel_launch(void* const* d_in, const int* in_sizes, int n_in,
                              void* d_out, int out_size)
{
    const float* x    = (const float*)d_in[0];
    const int*   erow = (const int*)  d_in[1];
    const int*   ecol = (const int*)  d_in[2];
    const float* eval = (const float*)d_in[3];
    const float* W    = (const float*)d_in[4];
    const float* b    = (const float*)d_in[5];
    float*       out  = (float*)d_out;

    float* xw;  cudaGetSymbolAddress((void**)&xw, g_xw);
    int*   cnt; cudaGetSymbolAddress((void**)&cnt, g_cnt);

    if (g_side == nullptr) {
        cudaStreamCreateWithFlags(&g_side, cudaStreamNonBlocking);
        cudaEventCreateWithFlags(&g_evFork, cudaEventDisableTiming);
        cudaEventCreateWithFlags(&g_evJoin, cudaEventDisableTiming);
        cudaFuncSetAttribute(linear_kernel,
                             cudaFuncAttributeMaxDynamicSharedMemorySize, LIN_SMEM);
    }

    // ---- fork ----
    cudaEventRecord(g_evFork, 0);
    cudaStreamWaitEvent(g_side, g_evFork, 0);

    // branch B (side): bias tile, then bf16 3-pass tensor GEMM
    btile_kernel<<<1, 1024, 0, g_side>>>(b);
    linear_kernel<<<LIN_BLOCKS, 256, LIN_SMEM, g_side>>>(x, W, xw);
    cudaEventRecord(g_evJoin, g_side);

    // branch A (main): memset counters -> bucket build (~28us)
    cudaMemsetAsync(cnt, 0, N_NODES * sizeof(int));
    bucket_kernel<<<(N_EDGES + 255) / 256, 256>>>(erow, ecol, eval);

    // ---- join, then gather ----
    cudaStreamWaitEvent(0, g_evJoin, 0);
    {
        int warps  = (N_NODES + 1) / 2;          // 2 rows per warp
        int blocks = (warps * 32 + 255) / 256;
        gather_kernel<<<blocks, 256>>>(xw, (float4*)out);
    }
}

// round 16
// speedup vs baseline: 1.3744x; 1.3744x over previous
#include <cuda_runtime.h>
#include <cuda_bf16.h>
#include <cstdint>

#define N_NODES 100000
#define N_EDGES 1600000
#define IN_DIM  128
#define OUT_DIM 64
#define BUCKET_CAP 64
#define LIN_BLOCKS ((N_NODES + 255) / 256)         // 391 GEMM blocks (256 nodes each)

// Scratch (allocation-free rule: __device__ globals)
__device__ float              g_xw[(size_t)N_NODES * OUT_DIM];           // 25.6 MB
__device__ unsigned long long g_bucket[(size_t)N_NODES * BUCKET_CAP];    // 51.2 MB
__device__ int                g_cnt[N_NODES];                            // per-row counts

// ---------------------------------------------------------------------------
// Register-tiled FFMA GEMM (PROVEN 54.4us): xw = x@W + b. 256 threads,
// 256 nodes/block; thread (tm,tn) owns an 8-node x 8-output tile.
// ---------------------------------------------------------------------------
__global__ __launch_bounds__(256, 2) void linear_kernel(
    const float* __restrict__ x,
    const float* __restrict__ W,
    const float* __restrict__ b,
    float* __restrict__ xw)
{
    __shared__ float Ws[IN_DIM * OUT_DIM];   // 32 KB
    __shared__ float bs[OUT_DIM];
    int tid = threadIdx.x;

    const float4* W4  = (const float4*)W;
    float4*       Ws4 = (float4*)Ws;
    #pragma unroll
    for (int i = tid; i < (IN_DIM * OUT_DIM) / 4; i += 256) Ws4[i] = W4[i];
    if (tid < OUT_DIM) bs[tid] = b[tid];
    __syncthreads();

    int tn = tid & 7;
    int tm = tid >> 3;
    int n0 = blockIdx.x * 256 + tm * 8;

    unsigned long long acc[8][4];
    #pragma unroll
    for (int m = 0; m < 8; m++) {
        #pragma unroll
        for (int q = 0; q < 4; q++) {
            asm("mov.b64 %0, {%1, %2};" : "=l"(acc[m][q])
                : "f"(bs[tn * 8 + 2 * q]), "f"(bs[tn * 8 + 2 * q + 1]));
        }
    }

    bool valid[8];
    #pragma unroll
    for (int m = 0; m < 8; m++) valid[m] = (n0 + m) < N_NODES;

    const ulonglong2* Ws2 = (const ulonglong2*)Ws;

    #pragma unroll 1
    for (int k4 = 0; k4 < IN_DIM / 4; k4++) {
        float4 xv[8];
        #pragma unroll
        for (int m = 0; m < 8; m++) {
            xv[m] = valid[m]
                  ? __ldg(((const float4*)(x + (size_t)(n0 + m) * IN_DIM)) + k4)
                  : make_float4(0.f, 0.f, 0.f, 0.f);
        }
        #pragma unroll
        for (int j = 0; j < 4; j++) {
            int k = k4 * 4 + j;
            const ulonglong2* wr = Ws2 + (size_t)k * (OUT_DIM / 4) + tn * 2;
            ulonglong2 w0 = wr[0];
            ulonglong2 w1 = wr[1];
            #pragma unroll
            for (int m = 0; m < 8; m++) {
                float xk = (j == 0) ? xv[m].x : (j == 1) ? xv[m].y
                         : (j == 2) ? xv[m].z : xv[m].w;
                unsigned long long xx;
                asm("mov.b64 %0, {%1, %1};" : "=l"(xx) : "f"(xk));
                asm("fma.rn.f32x2 %0, %1, %2, %0;" : "+l"(acc[m][0]) : "l"(xx), "l"(w0.x));
                asm("fma.rn.f32x2 %0, %1, %2, %0;" : "+l"(acc[m][1]) : "l"(xx), "l"(w0.y));
                asm("fma.rn.f32x2 %0, %1, %2, %0;" : "+l"(acc[m][2]) : "l"(xx), "l"(w1.x));
                asm("fma.rn.f32x2 %0, %1, %2, %0;" : "+l"(acc[m][3]) : "l"(xx), "l"(w1.y));
            }
        }
    }

    #pragma unroll
    for (int m = 0; m < 8; m++) {
        if (!valid[m]) continue;
        ulonglong2* dst = (ulonglong2*)(xw + (size_t)(n0 + m) * OUT_DIM + tn * 8);
        ulonglong2 v0; v0.x = acc[m][0]; v0.y = acc[m][1];
        ulonglong2 v1; v1.x = acc[m][2]; v1.y = acc[m][3];
        dst[0] = v0;
        dst[1] = v1;
    }
}

// ---------------------------------------------------------------------------
// Bucket build: rank = atomicAdd(cnt[row]); {val,col} into fixed 64-slot
// bucket. No histogram, no scan.
// ---------------------------------------------------------------------------
__global__ __launch_bounds__(256) void bucket_kernel(
    const int* __restrict__ erow, const int* __restrict__ ecol,
    const float* __restrict__ eval)
{
    int e = blockIdx.x * blockDim.x + threadIdx.x;
    if (e >= N_EDGES) return;
    int r = erow[e];
    int rank = atomicAdd(&g_cnt[r], 1);
    if (rank < BUCKET_CAP) {
        unsigned long long p =
            ((unsigned long long)(unsigned)__float_as_int(eval[e]) << 32)
            | (unsigned)ecol[e];
        g_bucket[(size_t)r * BUCKET_CAP + rank] = p;
    }
}

// ---------------------------------------------------------------------------
// Gather: 2 rows/warp, speculative front-batched loads, 8-edge inner
// iteration with 4 independent xw loads in flight per thread (MLP 2->4).
// Bound padded to multiple of 8 (padding: col=0 -> L1-hot dummy, val=0 ->
// no-op FMA). Rare cnt>32 spill handled in a guarded second chunk.
// ---------------------------------------------------------------------------
__global__ __launch_bounds__(256) void gather_kernel(
    const float* __restrict__ xw,
    float4* __restrict__ out)
{
    int warp = (blockIdx.x * 256 + threadIdx.x) >> 5;
    int lane = threadIdx.x & 31;
    int half = lane >> 4;
    int l16  = lane & 15;
    int r0   = warp * 2;
    if (r0 >= N_NODES) return;

    int cnt0 = g_cnt[r0];
    int cnt1 = (r0 + 1 < N_NODES) ? g_cnt[r0 + 1] : 0;
    if (cnt0 > BUCKET_CAP) cnt0 = BUCKET_CAP;
    if (cnt1 > BUCKET_CAP) cnt1 = BUCKET_CAP;
    const unsigned long long* bkt0 = g_bucket + (size_t)r0 * BUCKET_CAP;
    const unsigned long long* bkt1 = bkt0 + BUCKET_CAP;
    unsigned long long p0 = __ldg(&bkt0[lane]);                           // speculative
    unsigned long long p1 = (r0 + 1 < N_NODES) ? __ldg(&bkt1[lane]) : 0;  // speculative

    #pragma unroll
    for (int rr = 0; rr < 2; rr++) {
        int row = r0 + rr;
        if (row >= N_NODES) break;
        int cnt = rr ? cnt1 : cnt0;
        unsigned long long p = rr ? p1 : p0;

        int rem = cnt < 32 ? cnt : 32;
        if (lane >= rem) p = 0;                  // mask stale/padding slots
        unsigned plo = (unsigned)p;              // col (0 if padding)
        unsigned phi = (unsigned)(p >> 32);      // val bits (0.0f if padding)

        float4 a0 = make_float4(0.f, 0.f, 0.f, 0.f);
        float4 a1 = make_float4(0.f, 0.f, 0.f, 0.f);
        float4 a2 = make_float4(0.f, 0.f, 0.f, 0.f);
        float4 a3 = make_float4(0.f, 0.f, 0.f, 0.f);

        int m8 = (rem + 7) & ~7;                 // pad to multiple of 8
        #pragma unroll 1
        for (int j = 0; j < m8; j += 8) {        // guard-free body, 4 loads in flight
            unsigned c0 = __shfl_sync(0xffffffffu, plo, j + half);
            unsigned v0 = __shfl_sync(0xffffffffu, phi, j + half);
            unsigned c1 = __shfl_sync(0xffffffffu, plo, j + 2 + half);
            unsigned v1 = __shfl_sync(0xffffffffu, phi, j + 2 + half);
            unsigned c2 = __shfl_sync(0xffffffffu, plo, j + 4 + half);
            unsigned v2 = __shfl_sync(0xffffffffu, phi, j + 4 + half);
            unsigned c3 = __shfl_sync(0xffffffffu, plo, j + 6 + half);
            unsigned v3 = __shfl_sync(0xffffffffu, phi, j + 6 + half);
            float4 x0 = __ldg(((const float4*)(xw + (size_t)c0 * OUT_DIM)) + l16);
            float4 x1 = __ldg(((const float4*)(xw + (size_t)c1 * OUT_DIM)) + l16);
            float4 x2 = __ldg(((const float4*)(xw + (size_t)c2 * OUT_DIM)) + l16);
            float4 x3 = __ldg(((const float4*)(xw + (size_t)c3 * OUT_DIM)) + l16);
            float f0 = __int_as_float((int)v0);
            float f1 = __int_as_float((int)v1);
            float f2 = __int_as_float((int)v2);
            float f3 = __int_as_float((int)v3);
            a0.x = fmaf(x0.x, f0, a0.x); a0.y = fmaf(x0.y, f0, a0.y);
            a0.z = fmaf(x0.z, f0, a0.z); a0.w = fmaf(x0.w, f0, a0.w);
            a1.x = fmaf(x1.x, f1, a1.x); a1.y = fmaf(x1.y, f1, a1.y);
            a1.z = fmaf(x1.z, f1, a1.z); a1.w = fmaf(x1.w, f1, a1.w);
            a2.x = fmaf(x2.x, f2, a2.x); a2.y = fmaf(x2.y, f2, a2.y);
            a2.z = fmaf(x2.z, f2, a2.z); a2.w = fmaf(x2.w, f2, a2.w);
            a3.x = fmaf(x3.x, f3, a3.x); a3.y = fmaf(x3.y, f3, a3.y);
            a3.z = fmaf(x3.z, f3, a3.z); a3.w = fmaf(x3.w, f3, a3.w);
        }

        // ---- rare spill chunk (cnt > 32, P ~ 2e-4) ----
        if (cnt > 32) {
            const unsigned long long* bkt = rr ? bkt1 : bkt0;
            int rem2 = cnt - 32;
            unsigned long long q = (lane < rem2) ? __ldg(&bkt[32 + lane]) : 0ULL;
            unsigned qlo = (unsigned)q;
            unsigned qhi = (unsigned)(q >> 32);
            int m42 = (rem2 + 3) & ~3;
            for (int j = 0; j < m42; j += 4) {
                unsigned c0 = __shfl_sync(0xffffffffu, qlo, j + half);
                unsigned v0 = __shfl_sync(0xffffffffu, qhi, j + half);
                unsigned c1 = __shfl_sync(0xffffffffu, qlo, j + 2 + half);
                unsigned v1 = __shfl_sync(0xffffffffu, qhi, j + 2 + half);
                float4 x0 = __ldg(((const float4*)(xw + (size_t)c0 * OUT_DIM)) + l16);
                float4 x1 = __ldg(((const float4*)(xw + (size_t)c1 * OUT_DIM)) + l16);
                float f0 = __int_as_float((int)v0);
                float f1 = __int_as_float((int)v1);
                a0.x = fmaf(x0.x, f0, a0.x); a0.y = fmaf(x0.y, f0, a0.y);
                a0.z = fmaf(x0.z, f0, a0.z); a0.w = fmaf(x0.w, f0, a0.w);
                a1.x = fmaf(x1.x, f1, a1.x); a1.y = fmaf(x1.y, f1, a1.y);
                a1.z = fmaf(x1.z, f1, a1.z); a1.w = fmaf(x1.w, f1, a1.w);
            }
        }

        float4 acc;
        acc.x = (a0.x + a1.x) + (a2.x + a3.x);
        acc.y = (a0.y + a1.y) + (a2.y + a3.y);
        acc.z = (a0.z + a1.z) + (a2.z + a3.z);
        acc.w = (a0.w + a1.w) + (a2.w + a3.w);
        acc.x += __shfl_xor_sync(0xffffffffu, acc.x, 16);
        acc.y += __shfl_xor_sync(0xffffffffu, acc.y, 16);
        acc.z += __shfl_xor_sync(0xffffffffu, acc.z, 16);
        acc.w += __shfl_xor_sync(0xffffffffu, acc.w, 16);

        if (half == 0) {
            acc.x = fmaxf(acc.x, 0.f);
            acc.y = fmaxf(acc.y, 0.f);
            acc.z = fmaxf(acc.z, 0.f);
            acc.w = fmaxf(acc.w, 0.f);
            out[(size_t)row * (OUT_DIM / 4) + l16] = acc;
        }
    }
}

// ---------------------------------------------------------------------------
static cudaStream_t g_side = nullptr;
static cudaEvent_t  g_evFork = nullptr;
static cudaEvent_t  g_evJoin = nullptr;

extern "C" void kernel_launch(void* const* d_in, const int* in_sizes, int n_in,
                              void* d_out, int out_size)
{
    const float* x    = (const float*)d_in[0];
    const int*   erow = (const int*)  d_in[1];
    const int*   ecol = (const int*)  d_in[2];
    const float* eval = (const float*)d_in[3];
    const float* W    = (const float*)d_in[4];
    const float* b    = (const float*)d_in[5];
    float*       out  = (float*)d_out;

    float* xw;  cudaGetSymbolAddress((void**)&xw, g_xw);
    int*   cnt; cudaGetSymbolAddress((void**)&cnt, g_cnt);

    if (g_side == nullptr) {
        cudaStreamCreateWithFlags(&g_side, cudaStreamNonBlocking);
        cudaEventCreateWithFlags(&g_evFork, cudaEventDisableTiming);
        cudaEventCreateWithFlags(&g_evJoin, cudaEventDisableTiming);
    }

    // ---- fork: bucket chain on SIDE stream; GEMM on MAIN stream so the
    //      long branch and gather stay in-stream (no join wait on the
    //      critical path — the side chain finishes first). ----
    cudaEventRecord(g_evFork, 0);
    cudaStreamWaitEvent(g_side, g_evFork, 0);

    // side: memset counters -> bucket build (~28us, hidden under GEMM)
    cudaMemsetAsync(cnt, 0, N_NODES * sizeof(int), g_side);
    bucket_kernel<<<(N_EDGES + 255) / 256, 256, 0, g_side>>>(erow, ecol, eval);
    cudaEventRecord(g_evJoin, g_side);

    // main: FFMA GEMM (~54us, the longer branch)
    linear_kernel<<<LIN_BLOCKS, 256>>>(x, W, b, xw);

    // join (resolves immediately — side finished under the GEMM), then gather
    cudaStreamWaitEvent(0, g_evJoin, 0);
    {
        int warps  = (N_NODES + 1) / 2;          // 2 rows per warp
        int blocks = (warps * 32 + 255) / 256;
        gather_kernel<<<blocks, 256>>>(xw, (float4*)out);
    }
}

// round 17
// speedup vs baseline: 1.6049x; 1.1677x over previous
#include <cuda_runtime.h>
#include <cuda_bf16.h>
#include <cstdint>

#define N_NODES 100000
#define N_EDGES 1600000
#define IN_DIM  128
#define OUT_DIM 64
#define BUCKET_CAP 64
#define LIN_BLOCKS ((N_NODES + 255) / 256)         // 391 GEMM blocks (256 nodes each)

// Scratch (allocation-free rule: __device__ globals).
// g_cnt starts ZERO (static init) and gather re-zeroes it after reading ->
// every kernel_launch call sees zeros without a memset node.
__device__ float              g_xw[(size_t)N_NODES * OUT_DIM];           // 25.6 MB
__device__ unsigned long long g_bucket[(size_t)N_NODES * BUCKET_CAP];    // 51.2 MB
__device__ int                g_cnt[N_NODES];                            // per-row counts

// ---------------------------------------------------------------------------
// Register-tiled FFMA GEMM (PROVEN 54.4us): xw = x@W + b. 256 threads,
// 256 nodes/block; thread (tm,tn) owns an 8-node x 8-output tile.
// ---------------------------------------------------------------------------
__global__ __launch_bounds__(256, 2) void linear_kernel(
    const float* __restrict__ x,
    const float* __restrict__ W,
    const float* __restrict__ b,
    float* __restrict__ xw)
{
    __shared__ float Ws[IN_DIM * OUT_DIM];   // 32 KB
    __shared__ float bs[OUT_DIM];
    int tid = threadIdx.x;

    const float4* W4  = (const float4*)W;
    float4*       Ws4 = (float4*)Ws;
    #pragma unroll
    for (int i = tid; i < (IN_DIM * OUT_DIM) / 4; i += 256) Ws4[i] = W4[i];
    if (tid < OUT_DIM) bs[tid] = b[tid];
    __syncthreads();

    int tn = tid & 7;
    int tm = tid >> 3;
    int n0 = blockIdx.x * 256 + tm * 8;

    unsigned long long acc[8][4];
    #pragma unroll
    for (int m = 0; m < 8; m++) {
        #pragma unroll
        for (int q = 0; q < 4; q++) {
            asm("mov.b64 %0, {%1, %2};" : "=l"(acc[m][q])
                : "f"(bs[tn * 8 + 2 * q]), "f"(bs[tn * 8 + 2 * q + 1]));
        }
    }

    bool valid[8];
    #pragma unroll
    for (int m = 0; m < 8; m++) valid[m] = (n0 + m) < N_NODES;

    const ulonglong2* Ws2 = (const ulonglong2*)Ws;

    #pragma unroll 1
    for (int k4 = 0; k4 < IN_DIM / 4; k4++) {
        float4 xv[8];
        #pragma unroll
        for (int m = 0; m < 8; m++) {
            xv[m] = valid[m]
                  ? __ldg(((const float4*)(x + (size_t)(n0 + m) * IN_DIM)) + k4)
                  : make_float4(0.f, 0.f, 0.f, 0.f);
        }
        #pragma unroll
        for (int j = 0; j < 4; j++) {
            int k = k4 * 4 + j;
            const ulonglong2* wr = Ws2 + (size_t)k * (OUT_DIM / 4) + tn * 2;
            ulonglong2 w0 = wr[0];
            ulonglong2 w1 = wr[1];
            #pragma unroll
            for (int m = 0; m < 8; m++) {
                float xk = (j == 0) ? xv[m].x : (j == 1) ? xv[m].y
                         : (j == 2) ? xv[m].z : xv[m].w;
                unsigned long long xx;
                asm("mov.b64 %0, {%1, %1};" : "=l"(xx) : "f"(xk));
                asm("fma.rn.f32x2 %0, %1, %2, %0;" : "+l"(acc[m][0]) : "l"(xx), "l"(w0.x));
                asm("fma.rn.f32x2 %0, %1, %2, %0;" : "+l"(acc[m][1]) : "l"(xx), "l"(w0.y));
                asm("fma.rn.f32x2 %0, %1, %2, %0;" : "+l"(acc[m][2]) : "l"(xx), "l"(w1.x));
                asm("fma.rn.f32x2 %0, %1, %2, %0;" : "+l"(acc[m][3]) : "l"(xx), "l"(w1.y));
            }
        }
    }

    #pragma unroll
    for (int m = 0; m < 8; m++) {
        if (!valid[m]) continue;
        ulonglong2* dst = (ulonglong2*)(xw + (size_t)(n0 + m) * OUT_DIM + tn * 8);
        ulonglong2 v0; v0.x = acc[m][0]; v0.y = acc[m][1];
        ulonglong2 v1; v1.x = acc[m][2]; v1.y = acc[m][3];
        dst[0] = v0;
        dst[1] = v1;
    }
}

// ---------------------------------------------------------------------------
// Bucket build: rank = atomicAdd(cnt[row]); {val,col} into fixed 64-slot
// bucket. No histogram, no scan. Counters are zero at entry (invariant
// maintained by gather_kernel re-zeroing them after use).
// ---------------------------------------------------------------------------
__global__ __launch_bounds__(256) void bucket_kernel(
    const int* __restrict__ erow, const int* __restrict__ ecol,
    const float* __restrict__ eval)
{
    int e = blockIdx.x * blockDim.x + threadIdx.x;
    if (e >= N_EDGES) return;
    int r = erow[e];
    int rank = atomicAdd(&g_cnt[r], 1);
    if (rank < BUCKET_CAP) {
        unsigned long long p =
            ((unsigned long long)(unsigned)__float_as_int(eval[e]) << 32)
            | (unsigned)ecol[e];
        g_bucket[(size_t)r * BUCKET_CAP + rank] = p;
    }
}

// ---------------------------------------------------------------------------
// Gather (R14-proven shape): 2 rows/warp, speculative front-batched loads,
// guard-free inner body padded to multiple of 4, rare cnt>32 spill path.
// After reading cnt, lane 0 zeroes it (restores the invariant for the next
// call — removes the memset node from the graph).
// ---------------------------------------------------------------------------
__global__ __launch_bounds__(256, 6) void gather_kernel(
    const float* __restrict__ xw,
    float4* __restrict__ out)
{
    int warp = (blockIdx.x * 256 + threadIdx.x) >> 5;
    int lane = threadIdx.x & 31;
    int half = lane >> 4;
    int l16  = lane & 15;
    int r0   = warp * 2;
    if (r0 >= N_NODES) return;

    int cnt0 = g_cnt[r0];
    int cnt1 = (r0 + 1 < N_NODES) ? g_cnt[r0 + 1] : 0;
    // restore the zero-invariant for the next launch (read happened above)
    if (lane == 0) {
        g_cnt[r0] = 0;
        if (r0 + 1 < N_NODES) g_cnt[r0 + 1] = 0;
    }
    if (cnt0 > BUCKET_CAP) cnt0 = BUCKET_CAP;
    if (cnt1 > BUCKET_CAP) cnt1 = BUCKET_CAP;
    const unsigned long long* bkt0 = g_bucket + (size_t)r0 * BUCKET_CAP;
    const unsigned long long* bkt1 = bkt0 + BUCKET_CAP;
    unsigned long long p0 = __ldg(&bkt0[lane]);                           // speculative
    unsigned long long p1 = (r0 + 1 < N_NODES) ? __ldg(&bkt1[lane]) : 0;  // speculative

    #pragma unroll
    for (int rr = 0; rr < 2; rr++) {
        int row = r0 + rr;
        if (row >= N_NODES) break;
        int cnt = rr ? cnt1 : cnt0;
        unsigned long long p = rr ? p1 : p0;

        int rem = cnt < 32 ? cnt : 32;
        if (lane >= rem) p = 0;                  // mask stale/padding slots
        unsigned plo = (unsigned)p;              // col (0 if padding)
        unsigned phi = (unsigned)(p >> 32);      // val bits (0.0f if padding)

        float4 a0 = make_float4(0.f, 0.f, 0.f, 0.f);
        float4 a1 = make_float4(0.f, 0.f, 0.f, 0.f);

        int m4 = (rem + 3) & ~3;                 // warp-uniform, pad to 4
        #pragma unroll 2
        for (int j = 0; j < m4; j += 4) {        // guard-free body
            unsigned c0 = __shfl_sync(0xffffffffu, plo, j + half);
            unsigned v0 = __shfl_sync(0xffffffffu, phi, j + half);
            unsigned c1 = __shfl_sync(0xffffffffu, plo, j + 2 + half);
            unsigned v1 = __shfl_sync(0xffffffffu, phi, j + 2 + half);
            float4 x0 = __ldg(((const float4*)(xw + (size_t)c0 * OUT_DIM)) + l16);
            float4 x1 = __ldg(((const float4*)(xw + (size_t)c1 * OUT_DIM)) + l16);
            float f0 = __int_as_float((int)v0);
            float f1 = __int_as_float((int)v1);
            a0.x = fmaf(x0.x, f0, a0.x); a0.y = fmaf(x0.y, f0, a0.y);
            a0.z = fmaf(x0.z, f0, a0.z); a0.w = fmaf(x0.w, f0, a0.w);
            a1.x = fmaf(x1.x, f1, a1.x); a1.y = fmaf(x1.y, f1, a1.y);
            a1.z = fmaf(x1.z, f1, a1.z); a1.w = fmaf(x1.w, f1, a1.w);
        }

        // ---- rare spill chunk (cnt > 32, P ~ 2e-4) ----
        if (cnt > 32) {
            const unsigned long long* bkt = rr ? bkt1 : bkt0;
            int rem2 = cnt - 32;
            unsigned long long q = (lane < rem2) ? __ldg(&bkt[32 + lane]) : 0ULL;
            unsigned qlo = (unsigned)q;
            unsigned qhi = (unsigned)(q >> 32);
            int m42 = (rem2 + 3) & ~3;
            for (int j = 0; j < m42; j += 4) {
                unsigned c0 = __shfl_sync(0xffffffffu, qlo, j + half);
                unsigned v0 = __shfl_sync(0xffffffffu, qhi, j + half);
                unsigned c1 = __shfl_sync(0xffffffffu, qlo, j + 2 + half);
                unsigned v1 = __shfl_sync(0xffffffffu, qhi, j + 2 + half);
                float4 x0 = __ldg(((const float4*)(xw + (size_t)c0 * OUT_DIM)) + l16);
                float4 x1 = __ldg(((const float4*)(xw + (size_t)c1 * OUT_DIM)) + l16);
                float f0 = __int_as_float((int)v0);
                float f1 = __int_as_float((int)v1);
                a0.x = fmaf(x0.x, f0, a0.x); a0.y = fmaf(x0.y, f0, a0.y);
                a0.z = fmaf(x0.z, f0, a0.z); a0.w = fmaf(x0.w, f0, a0.w);
                a1.x = fmaf(x1.x, f1, a1.x); a1.y = fmaf(x1.y, f1, a1.y);
                a1.z = fmaf(x1.z, f1, a1.z); a1.w = fmaf(x1.w, f1, a1.w);
            }
        }

        float4 acc;
        acc.x = a0.x + a1.x; acc.y = a0.y + a1.y;
        acc.z = a0.z + a1.z; acc.w = a0.w + a1.w;
        acc.x += __shfl_xor_sync(0xffffffffu, acc.x, 16);
        acc.y += __shfl_xor_sync(0xffffffffu, acc.y, 16);
        acc.z += __shfl_xor_sync(0xffffffffu, acc.z, 16);
        acc.w += __shfl_xor_sync(0xffffffffu, acc.w, 16);

        if (half == 0) {
            acc.x = fmaxf(acc.x, 0.f);
            acc.y = fmaxf(acc.y, 0.f);
            acc.z = fmaxf(acc.z, 0.f);
            acc.w = fmaxf(acc.w, 0.f);
            out[(size_t)row * (OUT_DIM / 4) + l16] = acc;
        }
    }
}

// ---------------------------------------------------------------------------
static cudaStream_t g_side = nullptr;
static cudaEvent_t  g_evFork = nullptr;
static cudaEvent_t  g_evJoin = nullptr;

extern "C" void kernel_launch(void* const* d_in, const int* in_sizes, int n_in,
                              void* d_out, int out_size)
{
    const float* x    = (const float*)d_in[0];
    const int*   erow = (const int*)  d_in[1];
    const int*   ecol = (const int*)  d_in[2];
    const float* eval = (const float*)d_in[3];
    const float* W    = (const float*)d_in[4];
    const float* b    = (const float*)d_in[5];
    float*       out  = (float*)d_out;

    float* xw;  cudaGetSymbolAddress((void**)&xw, g_xw);

    if (g_side == nullptr) {
        cudaStreamCreateWithFlags(&g_side, cudaStreamNonBlocking);
        cudaEventCreateWithFlags(&g_evFork, cudaEventDisableTiming);
        cudaEventCreateWithFlags(&g_evJoin, cudaEventDisableTiming);
    }

    // ---- fork (R14 layout: GEMM on side, bucket chain on main) ----
    cudaEventRecord(g_evFork, 0);
    cudaStreamWaitEvent(g_side, g_evFork, 0);

    // side: FFMA GEMM (~54us, the longer branch)
    linear_kernel<<<LIN_BLOCKS, 256, 0, g_side>>>(x, W, b, xw);
    cudaEventRecord(g_evJoin, g_side);

    // main: bucket build (~26us; counters already zero via gather invariant)
    bucket_kernel<<<(N_EDGES + 255) / 256, 256>>>(erow, ecol, eval);

    // ---- join, then gather ----
    cudaStreamWaitEvent(0, g_evJoin, 0);
    {
        int warps  = (N_NODES + 1) / 2;          // 2 rows per warp
        int blocks = (warps * 32 + 255) / 256;
        gather_kernel<<<blocks, 256>>>(xw, (float4*)out);
    }
}